// round 10
// baseline (speedup 1.0000x reference)
#include <cuda_runtime.h>
#include <cuda_bf16.h>

namespace {

constexpr int Bn  = 512;
constexpr int DKn = 256;
constexpr int DVn = 256;
constexpr int Pn  = 2048;
constexpr float SCALEf = 1.0f / 16.0f;   // 1/sqrt(256)

__device__ __forceinline__ float4 ldcs4(const float* p) {
    return __ldcs(reinterpret_cast<const float4*>(p));
}

__global__ void __launch_bounds__(256, 2)
attn_kernel(const float* __restrict__ Q,
            const float* __restrict__ K,
            const float* __restrict__ V,
            const int*   __restrict__ mask,
            float*       __restrict__ out)
{
    __shared__ float sQ[DKn];
    __shared__ float sW[Pn];
    __shared__ float sRed[8];

    const int b    = blockIdx.x;
    const int t    = threadIdx.x;
    const int lane = t & 31;
    const int warp = t >> 5;

    // ---- Q row into smem ----
    sQ[t] = Q[(size_t)b * DKn + t];
    __syncthreads();

    const int pA = 4 * t;
    const int pB = (Pn / 2) + 4 * t;
    const float* __restrict__ KbA = K + (size_t)b * DKn * Pn + pA;
    const float* __restrict__ KbB = K + (size_t)b * DKn * Pn + pB;

    // prefetch mask early (hides the mask stream behind the K stream)
    const int4 mA = *reinterpret_cast<const int4*>(mask + (size_t)b * Pn + pA);
    const int4 mB = *reinterpret_cast<const int4*>(mask + (size_t)b * Pn + pB);

    // ---- Phase 1: depth-2 software-pipelined K stream (evict-first) ----
    float4 bufA[8], bufB[8];
    float4 aA = make_float4(0.f, 0.f, 0.f, 0.f);
    float4 aB = make_float4(0.f, 0.f, 0.f, 0.f);

#define LOAD_CHUNK(BUF, D0)                                                        \
    {                                                                              \
        _Pragma("unroll")                                                          \
        for (int i = 0; i < 4; ++i) {                                              \
            BUF[2*i]   = ldcs4(KbA + (size_t)((D0)+i) * Pn);                       \
            BUF[2*i+1] = ldcs4(KbB + (size_t)((D0)+i) * Pn);                       \
        }                                                                          \
    }
#define FMA_CHUNK(BUF, D0)                                                         \
    {                                                                              \
        _Pragma("unroll")                                                          \
        for (int i = 0; i < 4; ++i) {                                              \
            const float q = sQ[(D0)+i];                                            \
            aA.x = fmaf(q, BUF[2*i].x,   aA.x);                                    \
            aA.y = fmaf(q, BUF[2*i].y,   aA.y);                                    \
            aA.z = fmaf(q, BUF[2*i].z,   aA.z);                                    \
            aA.w = fmaf(q, BUF[2*i].w,   aA.w);                                    \
            aB.x = fmaf(q, BUF[2*i+1].x, aB.x);                                    \
            aB.y = fmaf(q, BUF[2*i+1].y, aB.y);                                    \
            aB.z = fmaf(q, BUF[2*i+1].z, aB.z);                                    \
            aB.w = fmaf(q, BUF[2*i+1].w, aB.w);                                    \
        }                                                                          \
    }

    LOAD_CHUNK(bufA, 0)
    #pragma unroll 1
    for (int d0 = 0; d0 < DKn; d0 += 8) {
        LOAD_CHUNK(bufB, d0 + 4)
        FMA_CHUNK(bufA, d0)
        if (d0 + 8 < DKn) LOAD_CHUNK(bufA, d0 + 8)
        FMA_CHUNK(bufB, d0 + 4)
    }
#undef LOAD_CHUNK
#undef FMA_CHUNK

    // ---- multiplicative mask + scale (masked -> exactly 0.0, NOT -inf) ----
    float e[8];
    e[0] = mA.x ? aA.x * SCALEf : 0.f;
    e[1] = mA.y ? aA.y * SCALEf : 0.f;
    e[2] = mA.z ? aA.z * SCALEf : 0.f;
    e[3] = mA.w ? aA.w * SCALEf : 0.f;
    e[4] = mB.x ? aB.x * SCALEf : 0.f;
    e[5] = mB.y ? aB.y * SCALEf : 0.f;
    e[6] = mB.z ? aB.z * SCALEf : 0.f;
    e[7] = mB.w ? aB.w * SCALEf : 0.f;

    // ---- Phase 2: softmax over 2048 ----
    float lmax = e[0];
    #pragma unroll
    for (int i = 1; i < 8; ++i) lmax = fmaxf(lmax, e[i]);
    float v = lmax;
    #pragma unroll
    for (int o = 16; o; o >>= 1) v = fmaxf(v, __shfl_xor_sync(0xffffffffu, v, o));
    if (lane == 0) sRed[warp] = v;
    __syncthreads();
    float gmax = sRed[0];
    #pragma unroll
    for (int i = 1; i < 8; ++i) gmax = fmaxf(gmax, sRed[i]);
    __syncthreads();   // sRed reused for sum

    float w[8];
    float lsum = 0.f;
    #pragma unroll
    for (int i = 0; i < 8; ++i) {
        w[i] = __expf(e[i] - gmax);
        lsum += w[i];
    }
    *reinterpret_cast<float4*>(&sW[pA]) = make_float4(w[0], w[1], w[2], w[3]);
    *reinterpret_cast<float4*>(&sW[pB]) = make_float4(w[4], w[5], w[6], w[7]);

    v = lsum;
    #pragma unroll
    for (int o = 16; o; o >>= 1) v += __shfl_xor_sync(0xffffffffu, v, o);
    if (lane == 0) sRed[warp] = v;
    __syncthreads();   // publishes sW + sums
    float gsum = sRed[0];
    #pragma unroll
    for (int i = 1; i < 8; ++i) gsum += sRed[i];
    const float inv = 1.0f / gsum;

    // ---- Phase 3: 8 warps x 32 rows, groups of 4 rows with deferred reduces ----
    const float* __restrict__ Vb = V + (size_t)b * DVn * Pn;
    const int rbase = warp * (DVn / 8);

    #pragma unroll 1
    for (int g = 0; g < DVn / 8; g += 4) {
        float s[4];
        #pragma unroll
        for (int r = 0; r < 4; ++r) {
            const float* __restrict__ Vr = Vb + (size_t)(rbase + g + r) * Pn + lane * 4;
            float4 a4 = make_float4(0.f, 0.f, 0.f, 0.f);
            #pragma unroll
            for (int i = 0; i < Pn / 128; ++i) {   // 16 float4 loads per row
                const float4 vv = ldcs4(Vr + i * 128);
                const float4 ww = *reinterpret_cast<const float4*>(&sW[i * 128 + lane * 4]);
                a4.x = fmaf(ww.x, vv.x, a4.x);
                a4.y = fmaf(ww.y, vv.y, a4.y);
                a4.z = fmaf(ww.z, vv.z, a4.z);
                a4.w = fmaf(ww.w, vv.w, a4.w);
            }
            s[r] = (a4.x + a4.y) + (a4.z + a4.w);
        }
        // 4 independent shfl chains, interleaved
        #pragma unroll
        for (int o = 16; o; o >>= 1) {
            s[0] += __shfl_xor_sync(0xffffffffu, s[0], o);
            s[1] += __shfl_xor_sync(0xffffffffu, s[1], o);
            s[2] += __shfl_xor_sync(0xffffffffu, s[2], o);
            s[3] += __shfl_xor_sync(0xffffffffu, s[3], o);
        }
        if (lane == 0) {
            float* op = out + (size_t)b * DVn + rbase + g;
            op[0] = s[0] * inv;
            op[1] = s[1] * inv;
            op[2] = s[2] * inv;
            op[3] = s[3] * inv;
        }
    }
}

} // namespace

extern "C" void kernel_launch(void* const* d_in, const int* in_sizes, int n_in,
                              void* d_out, int out_size)
{
    const float* Q    = (const float*)d_in[0];
    const float* K    = (const float*)d_in[1];
    const float* V    = (const float*)d_in[2];
    const int*   mask = (const int*)d_in[3];
    float*       out  = (float*)d_out;

    attn_kernel<<<Bn, 256>>>(Q, K, V, mask, out);
}